// round 6
// baseline (speedup 1.0000x reference)
#include <cuda_runtime.h>

#define BB 16
#define MM 128
#define NH 256
#define EH 128
#define RR (BB*MM)          // 2048

// L2-resident scratch
__device__ __align__(128) float g_sA  [RR];
__device__ __align__(128) float g_aggE[RR * EH];
__device__ __align__(128) float g_hE  [RR * EH];
__device__ __align__(128) float g_pNM [4][RR * NH];   // X@Wv partials (K z-split)
__device__ __align__(128) float g_pHN [2][RR * NH];   // A^T@nodeMap partials (i-split)
__device__ __align__(128) float g_pO  [10][RR * NH];  // final-GEMM partials

// ---------------------------------------------------------------------------
// aggE[r,e] = sum_i A[b,i,j]*E[b,i,j,e]  (streams 128MB of E once) + sA
// ---------------------------------------------------------------------------
__global__ __launch_bounds__(256) void k_agge(const float* __restrict__ A,
                                              const float* __restrict__ E) {
    int r = blockIdx.x;
    int b = r >> 7, j = r & 127;
    __shared__ float Ac[MM];
    __shared__ float red[8][EH];
    int t = threadIdx.x;
    if (t < MM) Ac[t] = A[(b * MM + t) * MM + j];
    __syncthreads();

    int lane = t & 31, grp = t >> 5;
    const float* Eb = E + ((size_t)b * MM * MM + j) * EH;
    float4 acc = {0.f, 0.f, 0.f, 0.f};
#pragma unroll
    for (int ii = 0; ii < MM; ii += 16) {
        int i0 = ii + grp, i1 = ii + 8 + grp;
        float4 v0 = *(const float4*)(Eb + (size_t)i0 * MM * EH + lane * 4);
        float4 v1 = *(const float4*)(Eb + (size_t)i1 * MM * EH + lane * 4);
        float a0 = Ac[i0], a1 = Ac[i1];
        acc.x += a0 * v0.x + a1 * v1.x;
        acc.y += a0 * v0.y + a1 * v1.y;
        acc.z += a0 * v0.z + a1 * v1.z;
        acc.w += a0 * v0.w + a1 * v1.w;
    }
    *(float4*)&red[grp][lane * 4] = acc;
    __syncthreads();
    if (t < EH) {
        float s = 0.f;
#pragma unroll
        for (int g = 0; g < 8; g++) s += red[g][t];
        g_aggE[(size_t)r * EH + t] = s;
    }
    if (t == 0) {
        float s = 0.f;
#pragma unroll
        for (int i = 0; i < MM; i++) s += Ac[i];
        g_sA[r] = s;
    }
}

// ---------------------------------------------------------------------------
// Unified GEMM: BM=64, BN=64, BK=16, 256 threads, 4x4 micro, double-buffered.
//   AMODE: 0 plain   1 relu(A)   2 relu(A0+A1)
//   BMODE: 0 plain   1 B0+B1+B2+B3+vb[col]
//   EMODE: 0 store   1 relu(acc + sA[r]*eb[col])
//   BATCH: A = adjacency [b][k(i)][row(j)], B rows are per-batch global (b*128+i)
//   z = blockIdx.z: K chunk of KT*16; output offset z*pzStride.
// ---------------------------------------------------------------------------
template <int AMODE, int BMODE, int EMODE, bool BATCH>
__global__ __launch_bounds__(256) void gmm(
    const float* __restrict__ A0, const float* __restrict__ A1, int lda,
    const float* __restrict__ B0, const float* __restrict__ B1,
    const float* __restrict__ B2, const float* __restrict__ B3, int ldb,
    const float* __restrict__ vb, const float* __restrict__ eb,
    float* __restrict__ P, int ldp, size_t pzStride,
    int kaOff, int kbOff, int KT)
{
    __shared__ float As[2][16][68];
    __shared__ float Bs[2][16][64];

    int tid = threadIdx.x;
    int tx = tid & 15, ty = tid >> 4;
    int rowBase = blockIdx.x * 64, colBase = blockIdx.y * 64;
    int z = blockIdx.z;
    int ka = kaOff + z * KT * 16;
    int kb = kbOff + z * KT * 16;
    P += (size_t)z * pzStride;

    // ---- A pointers ----
    int kA = tid >> 4, j4 = (tid & 15) * 4;   // BATCH layout
    int arow = tid >> 2, ak4 = (tid & 3) * 4; // row-major layout
    const float* Ap;
    const float* Ap1 = nullptr;
    if (BATCH) {
        int b = rowBase >> 7, jloc = rowBase & 127;
        Ap = A0 + (size_t)b * MM * MM + (size_t)(ka + kA) * MM + jloc + j4;
    } else {
        Ap = A0 + (size_t)(rowBase + arow) * lda + ka + ak4;
        if (AMODE == 2) Ap1 = A1 + (size_t)(rowBase + arow) * lda + ka + ak4;
    }

    // ---- B pointers ----
    int kB = tid >> 4, c4 = (tid & 15) * 4;
    size_t bb = BATCH ? (size_t)(rowBase >> 7) * MM * (size_t)ldb : 0;
    size_t bOff = bb + (size_t)(kb + kB) * ldb + colBase + c4;
    const float* Bp  = B0 + bOff;
    const float* Bp1 = (BMODE == 1) ? B1 + bOff : nullptr;
    const float* Bp2 = (BMODE == 1) ? B2 + bOff : nullptr;
    const float* Bp3 = (BMODE == 1) ? B3 + bOff : nullptr;
    float4 vb4 = {0, 0, 0, 0};
    if (BMODE == 1) vb4 = *(const float4*)&vb[colBase + c4];

    auto ldA = [&]() {
        float4 v = *(const float4*)Ap;
        if (AMODE == 2) {
            float4 s = *(const float4*)Ap1;
            v.x += s.x; v.y += s.y; v.z += s.z; v.w += s.w;
        }
        if (AMODE >= 1) {
            v.x = fmaxf(v.x, 0.f); v.y = fmaxf(v.y, 0.f);
            v.z = fmaxf(v.z, 0.f); v.w = fmaxf(v.w, 0.f);
        }
        return v;
    };
    auto ldB = [&]() {
        float4 v = *(const float4*)Bp;
        if (BMODE == 1) {
            float4 a = *(const float4*)Bp1;
            float4 b = *(const float4*)Bp2;
            float4 c = *(const float4*)Bp3;
            v.x += a.x + b.x + c.x + vb4.x;
            v.y += a.y + b.y + c.y + vb4.y;
            v.z += a.z + b.z + c.z + vb4.z;
            v.w += a.w + b.w + c.w + vb4.w;
        }
        return v;
    };
    auto advance = [&]() {
        Ap += BATCH ? 16 * MM : 16;
        if (AMODE == 2) Ap1 += 16;
        size_t st = (size_t)16 * ldb;
        Bp += st;
        if (BMODE == 1) { Bp1 += st; Bp2 += st; Bp3 += st; }
    };

    float acc[4][4] = {};
    float4 ra, rb;

    ra = ldA(); rb = ldB();
    if (BATCH) {
        *(float4*)&As[0][kA][j4] = ra;
    } else {
        As[0][ak4 + 0][arow] = ra.x; As[0][ak4 + 1][arow] = ra.y;
        As[0][ak4 + 2][arow] = ra.z; As[0][ak4 + 3][arow] = ra.w;
    }
    *(float4*)&Bs[0][kB][c4] = rb;
    __syncthreads();

    for (int t = 0; t < KT; t++) {
        int cur = t & 1;
        bool more = (t + 1 < KT);
        if (more) { advance(); ra = ldA(); rb = ldB(); }
#pragma unroll
        for (int kk = 0; kk < 16; kk++) {
            float4 a4 = *(const float4*)&As[cur][kk][ty * 4];
            float4 b4 = *(const float4*)&Bs[cur][kk][tx * 4];
            float am[4] = {a4.x, a4.y, a4.z, a4.w};
            float bn[4] = {b4.x, b4.y, b4.z, b4.w};
#pragma unroll
            for (int i = 0; i < 4; i++)
#pragma unroll
                for (int jj = 0; jj < 4; jj++)
                    acc[i][jj] += am[i] * bn[jj];
        }
        if (more) {
            int nxt = cur ^ 1;
            if (BATCH) {
                *(float4*)&As[nxt][kA][j4] = ra;
            } else {
                As[nxt][ak4 + 0][arow] = ra.x; As[nxt][ak4 + 1][arow] = ra.y;
                As[nxt][ak4 + 2][arow] = ra.z; As[nxt][ak4 + 3][arow] = ra.w;
            }
            *(float4*)&Bs[nxt][kB][c4] = rb;
        }
        __syncthreads();
    }

    float4 eb4 = {0, 0, 0, 0};
    if (EMODE == 1) eb4 = *(const float4*)&eb[colBase + tx * 4];
#pragma unroll
    for (int i = 0; i < 4; i++) {
        int r = rowBase + ty * 4 + i;
        float4 v = {acc[i][0], acc[i][1], acc[i][2], acc[i][3]};
        if (EMODE == 1) {
            float sa = g_sA[r];
            v.x = fmaxf(v.x + sa * eb4.x, 0.f);
            v.y = fmaxf(v.y + sa * eb4.y, 0.f);
            v.z = fmaxf(v.z + sa * eb4.z, 0.f);
            v.w = fmaxf(v.w + sa * eb4.w, 0.f);
        }
        *(float4*)&P[(size_t)r * ldp + colBase + tx * 4] = v;
    }
}

// ---------------------------------------------------------------------------
// final: out = (sum of 10 partial slots + Wu_b[n]) * w[r]
// ---------------------------------------------------------------------------
__global__ __launch_bounds__(256) void k_final(const float* __restrict__ Wub,
                                               const float* __restrict__ w,
                                               float* __restrict__ out) {
    int r = blockIdx.x, n = threadIdx.x;
    size_t idx = (size_t)r * NH + n;
    float s = 0.f;
#pragma unroll
    for (int q = 0; q < 10; q++) s += g_pO[q][idx];
    out[idx] = (s + Wub[n]) * w[r];
}

// ---------------------------------------------------------------------------
extern "C" void kernel_launch(void* const* d_in, const int* in_sizes, int n_in,
                              void* d_out, int out_size) {
    const float* X    = (const float*)d_in[0];
    const float* E    = (const float*)d_in[1];
    const float* A    = (const float*)d_in[2];
    const float* w    = (const float*)d_in[3];
    const float* Wv_w = (const float*)d_in[4];
    const float* Wv_b = (const float*)d_in[5];
    const float* We_w = (const float*)d_in[6];
    const float* We_b = (const float*)d_in[7];
    const float* Wu_w = (const float*)d_in[8];
    const float* Wu_b = (const float*)d_in[9];
    float* out = (float*)d_out;

    float *p_aggE, *p_hE, *p_pNM, *p_pHN, *p_pO;
    cudaGetSymbolAddress((void**)&p_aggE, g_aggE);
    cudaGetSymbolAddress((void**)&p_hE,   g_hE);
    cudaGetSymbolAddress((void**)&p_pNM,  g_pNM);
    cudaGetSymbolAddress((void**)&p_pHN,  g_pHN);
    cudaGetSymbolAddress((void**)&p_pO,   g_pO);
    const size_t SL = (size_t)RR * NH;
    float* pNM0 = p_pNM;
    float* pNM1 = p_pNM + SL;
    float* pNM2 = p_pNM + 2 * SL;
    float* pNM3 = p_pNM + 3 * SL;
    float* pHN0 = p_pHN;
    float* pHN1 = p_pHN + SL;

    cudaStream_t sB, sC;
    cudaStreamCreateWithFlags(&sB, cudaStreamNonBlocking);
    cudaStreamCreateWithFlags(&sC, cudaStreamNonBlocking);
    cudaEvent_t e0, eB, eC;
    cudaEventCreateWithFlags(&e0, cudaEventDisableTiming);
    cudaEventCreateWithFlags(&eB, cudaEventDisableTiming);
    cudaEventCreateWithFlags(&eC, cudaEventDisableTiming);

    dim3 gZ4(RR / 64, NH / 64, 4);   // (32,4,4) = 512 CTAs
    dim3 gZ2(RR / 64, NH / 64, 2);   // (32,4,2) = 256
    dim3 gHE(RR / 64, EH / 64, 1);   // (32,2)

    cudaEventRecord(e0, 0);
    cudaStreamWaitEvent(sB, e0, 0);
    cudaStreamWaitEvent(sC, e0, 0);

    // ---- sB: edge chain ----
    k_agge<<<RR, 256, 0, sB>>>(A, E);
    // hE = relu(aggE @ We + sA*We_b), K=128
    gmm<0,0,1,false><<<gHE, 256, 0, sB>>>(p_aggE, nullptr, EH,
                                          We_w, nullptr, nullptr, nullptr, EH,
                                          nullptr, We_b, p_hE, EH, 0, 0, 0, 8);
    // pO[8],pO[9] = hE @ Wu[256:384], K=128 z-split 2
    gmm<0,0,0,false><<<gZ2, 256, 0, sB>>>(p_hE, nullptr, EH,
                                          Wu_w, nullptr, nullptr, nullptr, NH,
                                          nullptr, nullptr, p_pO + 8 * SL, NH, SL, 0, 256, 4);
    cudaEventRecord(eB, sB);

    // ---- sC: X branch: relu(X) @ Wu[384:640] -> pO[4..7], K=256 z-split 4 ----
    gmm<1,0,0,false><<<gZ4, 256, 0, sC>>>(X, nullptr, NH,
                                          Wu_w, nullptr, nullptr, nullptr, NH,
                                          nullptr, nullptr, p_pO + 4 * SL, NH, SL, 0, 384, 4);
    cudaEventRecord(eC, sC);

    // ---- s0: node chain ----
    // pNM[0..3] = X @ Wv, K=256 z-split 4
    gmm<0,0,0,false><<<gZ4, 256>>>(X, nullptr, NH,
                                   Wv_w, nullptr, nullptr, nullptr, NH,
                                   nullptr, nullptr, p_pNM, NH, SL, 0, 0, 4);
    // pHN[0..1] = A^T @ (pNM0+..+pNM3+Wv_b), per-batch, K(i)=128 z-split 2
    gmm<0,1,0,true><<<gZ2, 256>>>(A, nullptr, MM,
                                  pNM0, pNM1, pNM2, pNM3, NH,
                                  Wv_b, nullptr, p_pHN, NH, SL, 0, 0, 4);
    // pO[0..3] = relu(pHN0+pHN1) @ Wu[0:256], K=256 z-split 4
    gmm<2,0,0,false><<<gZ4, 256>>>(pHN0, pHN1, NH,
                                   Wu_w, nullptr, nullptr, nullptr, NH,
                                   nullptr, nullptr, p_pO, NH, SL, 0, 0, 4);

    // ---- join + epilogue ----
    cudaStreamWaitEvent(0, eB, 0);
    cudaStreamWaitEvent(0, eC, 0);
    k_final<<<RR, 256>>>(Wu_b, w, out);

    cudaEventDestroy(e0); cudaEventDestroy(eB); cudaEventDestroy(eC);
    cudaStreamDestroy(sB); cudaStreamDestroy(sC);
}

// round 7
// speedup vs baseline: 1.0004x; 1.0004x over previous
#include <cuda_runtime.h>

#define BB 16
#define MM 128
#define NH 256
#define EH 128
#define RR (BB*MM)          // 2048

// L2-resident scratch
__device__ __align__(128) float g_sA  [RR];
__device__ __align__(128) float g_aggE[RR * EH];
__device__ __align__(128) float g_hE  [RR * EH];
__device__ __align__(128) float g_pNM [4][RR * NH];   // X@Wv partials (K z-split)
__device__ __align__(128) float g_pHN [2][RR * NH];   // A^T@nodeMap partials (i-split)
__device__ __align__(128) float g_pO  [10][RR * NH];  // final-GEMM partials

// ---------------------------------------------------------------------------
// aggE[r,e] = sum_i A[b,i,j]*E[b,i,j,e]  (streams 128MB of E once) + sA
// ---------------------------------------------------------------------------
__global__ __launch_bounds__(256) void k_agge(const float* __restrict__ A,
                                              const float* __restrict__ E) {
    int r = blockIdx.x;
    int b = r >> 7, j = r & 127;
    __shared__ float Ac[MM];
    __shared__ float red[8][EH];
    int t = threadIdx.x;
    if (t < MM) Ac[t] = A[(b * MM + t) * MM + j];
    __syncthreads();

    int lane = t & 31, grp = t >> 5;
    const float* Eb = E + ((size_t)b * MM * MM + j) * EH;
    float4 acc = {0.f, 0.f, 0.f, 0.f};
#pragma unroll
    for (int ii = 0; ii < MM; ii += 16) {
        int i0 = ii + grp, i1 = ii + 8 + grp;
        float4 v0 = *(const float4*)(Eb + (size_t)i0 * MM * EH + lane * 4);
        float4 v1 = *(const float4*)(Eb + (size_t)i1 * MM * EH + lane * 4);
        float a0 = Ac[i0], a1 = Ac[i1];
        acc.x += a0 * v0.x + a1 * v1.x;
        acc.y += a0 * v0.y + a1 * v1.y;
        acc.z += a0 * v0.z + a1 * v1.z;
        acc.w += a0 * v0.w + a1 * v1.w;
    }
    *(float4*)&red[grp][lane * 4] = acc;
    __syncthreads();
    if (t < EH) {
        float s = 0.f;
#pragma unroll
        for (int g = 0; g < 8; g++) s += red[g][t];
        g_aggE[(size_t)r * EH + t] = s;
    }
    if (t == 0) {
        float s = 0.f;
#pragma unroll
        for (int i = 0; i < MM; i++) s += Ac[i];
        g_sA[r] = s;
    }
}

// ---------------------------------------------------------------------------
// Unified GEMM: BM=64, BN=64, BK=16, 256 threads, 4x4 micro, double-buffered.
//   AMODE: 0 plain   1 relu(A)   2 relu(A0+A1)
//   BMODE: 0 plain   1 B0+B1+B2+B3+vb[col]
//   EMODE: 0 store   1 relu(acc + sA[r]*eb[col])
//   BATCH: A = adjacency [b][k(i)][row(j)], B rows are per-batch global (b*128+i)
//   z = blockIdx.z: K chunk of KT*16; output offset z*pzStride.
// ---------------------------------------------------------------------------
template <int AMODE, int BMODE, int EMODE, bool BATCH>
__global__ __launch_bounds__(256) void gmm(
    const float* __restrict__ A0, const float* __restrict__ A1, int lda,
    const float* __restrict__ B0, const float* __restrict__ B1,
    const float* __restrict__ B2, const float* __restrict__ B3, int ldb,
    const float* __restrict__ vb, const float* __restrict__ eb,
    float* __restrict__ P, int ldp, size_t pzStride,
    int kaOff, int kbOff, int KT)
{
    __shared__ float As[2][16][68];
    __shared__ float Bs[2][16][64];

    int tid = threadIdx.x;
    int tx = tid & 15, ty = tid >> 4;
    int rowBase = blockIdx.x * 64, colBase = blockIdx.y * 64;
    int z = blockIdx.z;
    int ka = kaOff + z * KT * 16;
    int kb = kbOff + z * KT * 16;
    P += (size_t)z * pzStride;

    // ---- A pointers ----
    int kA = tid >> 4, j4 = (tid & 15) * 4;   // BATCH layout
    int arow = tid >> 2, ak4 = (tid & 3) * 4; // row-major layout
    const float* Ap;
    const float* Ap1 = nullptr;
    if (BATCH) {
        int b = rowBase >> 7, jloc = rowBase & 127;
        Ap = A0 + (size_t)b * MM * MM + (size_t)(ka + kA) * MM + jloc + j4;
    } else {
        Ap = A0 + (size_t)(rowBase + arow) * lda + ka + ak4;
        if (AMODE == 2) Ap1 = A1 + (size_t)(rowBase + arow) * lda + ka + ak4;
    }

    // ---- B pointers ----
    int kB = tid >> 4, c4 = (tid & 15) * 4;
    size_t bb = BATCH ? (size_t)(rowBase >> 7) * MM * (size_t)ldb : 0;
    size_t bOff = bb + (size_t)(kb + kB) * ldb + colBase + c4;
    const float* Bp  = B0 + bOff;
    const float* Bp1 = (BMODE == 1) ? B1 + bOff : nullptr;
    const float* Bp2 = (BMODE == 1) ? B2 + bOff : nullptr;
    const float* Bp3 = (BMODE == 1) ? B3 + bOff : nullptr;
    float4 vb4 = {0, 0, 0, 0};
    if (BMODE == 1) vb4 = *(const float4*)&vb[colBase + c4];

    auto ldA = [&]() {
        float4 v = *(const float4*)Ap;
        if (AMODE == 2) {
            float4 s = *(const float4*)Ap1;
            v.x += s.x; v.y += s.y; v.z += s.z; v.w += s.w;
        }
        if (AMODE >= 1) {
            v.x = fmaxf(v.x, 0.f); v.y = fmaxf(v.y, 0.f);
            v.z = fmaxf(v.z, 0.f); v.w = fmaxf(v.w, 0.f);
        }
        return v;
    };
    auto ldB = [&]() {
        float4 v = *(const float4*)Bp;
        if (BMODE == 1) {
            float4 a = *(const float4*)Bp1;
            float4 b = *(const float4*)Bp2;
            float4 c = *(const float4*)Bp3;
            v.x += a.x + b.x + c.x + vb4.x;
            v.y += a.y + b.y + c.y + vb4.y;
            v.z += a.z + b.z + c.z + vb4.z;
            v.w += a.w + b.w + c.w + vb4.w;
        }
        return v;
    };
    auto advance = [&]() {
        Ap += BATCH ? 16 * MM : 16;
        if (AMODE == 2) Ap1 += 16;
        size_t st = (size_t)16 * ldb;
        Bp += st;
        if (BMODE == 1) { Bp1 += st; Bp2 += st; Bp3 += st; }
    };

    float acc[4][4] = {};
    float4 ra, rb;

    ra = ldA(); rb = ldB();
    if (BATCH) {
        *(float4*)&As[0][kA][j4] = ra;
    } else {
        As[0][ak4 + 0][arow] = ra.x; As[0][ak4 + 1][arow] = ra.y;
        As[0][ak4 + 2][arow] = ra.z; As[0][ak4 + 3][arow] = ra.w;
    }
    *(float4*)&Bs[0][kB][c4] = rb;
    __syncthreads();

    for (int t = 0; t < KT; t++) {
        int cur = t & 1;
        bool more = (t + 1 < KT);
        if (more) { advance(); ra = ldA(); rb = ldB(); }
#pragma unroll
        for (int kk = 0; kk < 16; kk++) {
            float4 a4 = *(const float4*)&As[cur][kk][ty * 4];
            float4 b4 = *(const float4*)&Bs[cur][kk][tx * 4];
            float am[4] = {a4.x, a4.y, a4.z, a4.w};
            float bn[4] = {b4.x, b4.y, b4.z, b4.w};
#pragma unroll
            for (int i = 0; i < 4; i++)
#pragma unroll
                for (int jj = 0; jj < 4; jj++)
                    acc[i][jj] += am[i] * bn[jj];
        }
        if (more) {
            int nxt = cur ^ 1;
            if (BATCH) {
                *(float4*)&As[nxt][kA][j4] = ra;
            } else {
                As[nxt][ak4 + 0][arow] = ra.x; As[nxt][ak4 + 1][arow] = ra.y;
                As[nxt][ak4 + 2][arow] = ra.z; As[nxt][ak4 + 3][arow] = ra.w;
            }
            *(float4*)&Bs[nxt][kB][c4] = rb;
        }
        __syncthreads();
    }

    float4 eb4 = {0, 0, 0, 0};
    if (EMODE == 1) eb4 = *(const float4*)&eb[colBase + tx * 4];
#pragma unroll
    for (int i = 0; i < 4; i++) {
        int r = rowBase + ty * 4 + i;
        float4 v = {acc[i][0], acc[i][1], acc[i][2], acc[i][3]};
        if (EMODE == 1) {
            float sa = g_sA[r];
            v.x = fmaxf(v.x + sa * eb4.x, 0.f);
            v.y = fmaxf(v.y + sa * eb4.y, 0.f);
            v.z = fmaxf(v.z + sa * eb4.z, 0.f);
            v.w = fmaxf(v.w + sa * eb4.w, 0.f);
        }
        *(float4*)&P[(size_t)r * ldp + colBase + tx * 4] = v;
    }
}

// ---------------------------------------------------------------------------
// final: out = (sum of 10 partial slots + Wu_b[n]) * w[r]
// ---------------------------------------------------------------------------
__global__ __launch_bounds__(256) void k_final(const float* __restrict__ Wub,
                                               const float* __restrict__ w,
                                               float* __restrict__ out) {
    int r = blockIdx.x, n = threadIdx.x;
    size_t idx = (size_t)r * NH + n;
    float s = 0.f;
#pragma unroll
    for (int q = 0; q < 10; q++) s += g_pO[q][idx];
    out[idx] = (s + Wub[n]) * w[r];
}

// ---------------------------------------------------------------------------
extern "C" void kernel_launch(void* const* d_in, const int* in_sizes, int n_in,
                              void* d_out, int out_size) {
    const float* X    = (const float*)d_in[0];
    const float* E    = (const float*)d_in[1];
    const float* A    = (const float*)d_in[2];
    const float* w    = (const float*)d_in[3];
    const float* Wv_w = (const float*)d_in[4];
    const float* Wv_b = (const float*)d_in[5];
    const float* We_w = (const float*)d_in[6];
    const float* We_b = (const float*)d_in[7];
    const float* Wu_w = (const float*)d_in[8];
    const float* Wu_b = (const float*)d_in[9];
    float* out = (float*)d_out;

    float *p_aggE, *p_hE, *p_pNM, *p_pHN, *p_pO;
    cudaGetSymbolAddress((void**)&p_aggE, g_aggE);
    cudaGetSymbolAddress((void**)&p_hE,   g_hE);
    cudaGetSymbolAddress((void**)&p_pNM,  g_pNM);
    cudaGetSymbolAddress((void**)&p_pHN,  g_pHN);
    cudaGetSymbolAddress((void**)&p_pO,   g_pO);
    const size_t SL = (size_t)RR * NH;
    float* pNM0 = p_pNM;
    float* pNM1 = p_pNM + SL;
    float* pNM2 = p_pNM + 2 * SL;
    float* pNM3 = p_pNM + 3 * SL;
    float* pHN0 = p_pHN;
    float* pHN1 = p_pHN + SL;

    cudaStream_t sB, sC;
    cudaStreamCreateWithFlags(&sB, cudaStreamNonBlocking);
    cudaStreamCreateWithFlags(&sC, cudaStreamNonBlocking);
    cudaEvent_t e0, eB, eC;
    cudaEventCreateWithFlags(&e0, cudaEventDisableTiming);
    cudaEventCreateWithFlags(&eB, cudaEventDisableTiming);
    cudaEventCreateWithFlags(&eC, cudaEventDisableTiming);

    dim3 gZ4(RR / 64, NH / 64, 4);   // (32,4,4) = 512 CTAs
    dim3 gZ2(RR / 64, NH / 64, 2);   // (32,4,2) = 256
    dim3 gHE(RR / 64, EH / 64, 1);   // (32,2)

    cudaEventRecord(e0, 0);
    cudaStreamWaitEvent(sB, e0, 0);
    cudaStreamWaitEvent(sC, e0, 0);

    // ---- sB: edge chain ----
    k_agge<<<RR, 256, 0, sB>>>(A, E);
    // hE = relu(aggE @ We + sA*We_b), K=128
    gmm<0,0,1,false><<<gHE, 256, 0, sB>>>(p_aggE, nullptr, EH,
                                          We_w, nullptr, nullptr, nullptr, EH,
                                          nullptr, We_b, p_hE, EH, 0, 0, 0, 8);
    // pO[8],pO[9] = hE @ Wu[256:384], K=128 z-split 2
    gmm<0,0,0,false><<<gZ2, 256, 0, sB>>>(p_hE, nullptr, EH,
                                          Wu_w, nullptr, nullptr, nullptr, NH,
                                          nullptr, nullptr, p_pO + 8 * SL, NH, SL, 0, 256, 4);
    cudaEventRecord(eB, sB);

    // ---- sC: X branch: relu(X) @ Wu[384:640] -> pO[4..7], K=256 z-split 4 ----
    gmm<1,0,0,false><<<gZ4, 256, 0, sC>>>(X, nullptr, NH,
                                          Wu_w, nullptr, nullptr, nullptr, NH,
                                          nullptr, nullptr, p_pO + 4 * SL, NH, SL, 0, 384, 4);
    cudaEventRecord(eC, sC);

    // ---- s0: node chain ----
    // pNM[0..3] = X @ Wv, K=256 z-split 4
    gmm<0,0,0,false><<<gZ4, 256>>>(X, nullptr, NH,
                                   Wv_w, nullptr, nullptr, nullptr, NH,
                                   nullptr, nullptr, p_pNM, NH, SL, 0, 0, 4);
    // pHN[0..1] = A^T @ (pNM0+..+pNM3+Wv_b), per-batch, K(i)=128 z-split 2
    gmm<0,1,0,true><<<gZ2, 256>>>(A, nullptr, MM,
                                  pNM0, pNM1, pNM2, pNM3, NH,
                                  Wv_b, nullptr, p_pHN, NH, SL, 0, 0, 4);
    // pO[0..3] = relu(pHN0+pHN1) @ Wu[0:256], K=256 z-split 4
    gmm<2,0,0,false><<<gZ4, 256>>>(pHN0, pHN1, NH,
                                   Wu_w, nullptr, nullptr, nullptr, NH,
                                   nullptr, nullptr, p_pO, NH, SL, 0, 0, 4);

    // ---- join + epilogue ----
    cudaStreamWaitEvent(0, eB, 0);
    cudaStreamWaitEvent(0, eC, 0);
    k_final<<<RR, 256>>>(Wu_b, w, out);

    cudaEventDestroy(e0); cudaEventDestroy(eB); cudaEventDestroy(eC);
    cudaStreamDestroy(sB); cudaStreamDestroy(sC);
}

// round 8
// speedup vs baseline: 1.1664x; 1.1659x over previous
#include <cuda_runtime.h>

#define BB 16
#define MM 128
#define NH 256
#define EH 128
#define RR (BB*MM)          // 2048

// L2-resident scratch
__device__ __align__(128) float g_sA  [RR];
__device__ __align__(128) float g_aggE[RR * EH];
__device__ __align__(128) float g_hE  [RR * EH];
__device__ __align__(128) float g_hN  [RR * NH];
__device__ __align__(128) float g_pNM [2][RR * NH];   // X@Wv partials (K z-split)
__device__ __align__(128) float g_pO  [5][RR * NH];   // final-GEMM partials

// ---------------------------------------------------------------------------
// Persistent E reduction: 512 CTAs grid-stride over r=0..2047.
// aggE[r,e] = sum_i A[b,i,j]*E[b,i,j,e];  sA[r] = sum_i A[b,i,j].
// Small SM footprint (~3.5 CTAs/SM) so GEMM streams co-run alongside.
// ---------------------------------------------------------------------------
__global__ __launch_bounds__(256) void k_agge(const float* __restrict__ A,
                                              const float* __restrict__ E) {
    __shared__ float Ac[MM];
    __shared__ float red[8][EH];
    int t = threadIdx.x;
    int lane = t & 31, grp = t >> 5;

    for (int r = blockIdx.x; r < RR; r += gridDim.x) {
        int b = r >> 7, j = r & 127;
        if (t < MM) Ac[t] = A[(b * MM + t) * MM + j];
        __syncthreads();

        const float* Eb = E + ((size_t)b * MM * MM + j) * EH;
        float4 acc = {0.f, 0.f, 0.f, 0.f};
#pragma unroll
        for (int ii = 0; ii < MM; ii += 16) {
            int i0 = ii + grp, i1 = ii + 8 + grp;
            float4 v0 = *(const float4*)(Eb + (size_t)i0 * MM * EH + lane * 4);
            float4 v1 = *(const float4*)(Eb + (size_t)i1 * MM * EH + lane * 4);
            float a0 = Ac[i0], a1 = Ac[i1];
            acc.x += a0 * v0.x + a1 * v1.x;
            acc.y += a0 * v0.y + a1 * v1.y;
            acc.z += a0 * v0.z + a1 * v1.z;
            acc.w += a0 * v0.w + a1 * v1.w;
        }
        *(float4*)&red[grp][lane * 4] = acc;
        __syncthreads();
        if (t < EH) {
            float s = 0.f;
#pragma unroll
            for (int g = 0; g < 8; g++) s += red[g][t];
            g_aggE[(size_t)r * EH + t] = s;
        }
        if (t == 0) {
            float s = 0.f;
#pragma unroll
            for (int i = 0; i < MM; i++) s += Ac[i];
            g_sA[r] = s;
        }
        __syncthreads();   // protect Ac/red before next iteration
    }
}

// ---------------------------------------------------------------------------
// Unified GEMM: BM=64, BN=64, BK=16, 256 threads, 4x4 micro, double-buffered.
//   AMODE: 0 plain   1 relu(A)
//   BMODE: 0 plain   1 B0+B1+vb[col]   (combine K-split partials + bias)
//   EMODE: 0 store   1 relu(acc + sA[r]*eb[col])   2 relu(acc)
//   BATCH: A = adjacency [b][k(i)][row(j)]; B rows global per-batch (b*128+k)
//   z = blockIdx.z: K chunk of KT*16; output offset z*pzStride.
// ---------------------------------------------------------------------------
template <int AMODE, int BMODE, int EMODE, bool BATCH>
__global__ __launch_bounds__(256) void gmm(
    const float* __restrict__ A0, int lda,
    const float* __restrict__ B0, const float* __restrict__ B1, int ldb,
    const float* __restrict__ vb, const float* __restrict__ eb,
    float* __restrict__ P, int ldp, size_t pzStride,
    int kaOff, int kbOff, int KT)
{
    __shared__ float As[2][16][68];
    __shared__ float Bs[2][16][64];

    int tid = threadIdx.x;
    int tx = tid & 15, ty = tid >> 4;
    int rowBase = blockIdx.x * 64, colBase = blockIdx.y * 64;
    int z = blockIdx.z;
    int ka = kaOff + z * KT * 16;
    int kb = kbOff + z * KT * 16;
    P += (size_t)z * pzStride;

    // ---- A pointers ----
    int kA = tid >> 4, j4 = (tid & 15) * 4;   // BATCH layout
    int arow = tid >> 2, ak4 = (tid & 3) * 4; // row-major layout
    const float* Ap;
    if (BATCH) {
        int b = rowBase >> 7, jloc = rowBase & 127;
        Ap = A0 + (size_t)b * MM * MM + (size_t)(ka + kA) * MM + jloc + j4;
    } else {
        Ap = A0 + (size_t)(rowBase + arow) * lda + ka + ak4;
    }

    // ---- B pointers ----
    int kB = tid >> 4, c4 = (tid & 15) * 4;
    size_t bb = BATCH ? (size_t)(rowBase >> 7) * MM * (size_t)ldb : 0;
    size_t bOff = bb + (size_t)(kb + kB) * ldb + colBase + c4;
    const float* Bp  = B0 + bOff;
    const float* Bp1 = (BMODE == 1) ? B1 + bOff : nullptr;
    float4 vb4 = {0, 0, 0, 0};
    if (BMODE == 1) vb4 = *(const float4*)&vb[colBase + c4];

    auto ldA = [&]() {
        float4 v = *(const float4*)Ap;
        if (AMODE == 1) {
            v.x = fmaxf(v.x, 0.f); v.y = fmaxf(v.y, 0.f);
            v.z = fmaxf(v.z, 0.f); v.w = fmaxf(v.w, 0.f);
        }
        return v;
    };
    auto ldB = [&]() {
        float4 v = *(const float4*)Bp;
        if (BMODE == 1) {
            float4 a = *(const float4*)Bp1;
            v.x += a.x + vb4.x; v.y += a.y + vb4.y;
            v.z += a.z + vb4.z; v.w += a.w + vb4.w;
        }
        return v;
    };
    auto advance = [&]() {
        Ap += BATCH ? 16 * MM : 16;
        size_t st = (size_t)16 * ldb;
        Bp += st;
        if (BMODE == 1) Bp1 += st;
    };

    float acc[4][4] = {};
    float4 ra, rb;

    ra = ldA(); rb = ldB();
    if (BATCH) {
        *(float4*)&As[0][kA][j4] = ra;
    } else {
        As[0][ak4 + 0][arow] = ra.x; As[0][ak4 + 1][arow] = ra.y;
        As[0][ak4 + 2][arow] = ra.z; As[0][ak4 + 3][arow] = ra.w;
    }
    *(float4*)&Bs[0][kB][c4] = rb;
    __syncthreads();

    for (int t = 0; t < KT; t++) {
        int cur = t & 1;
        bool more = (t + 1 < KT);
        if (more) { advance(); ra = ldA(); rb = ldB(); }
#pragma unroll
        for (int kk = 0; kk < 16; kk++) {
            float4 a4 = *(const float4*)&As[cur][kk][ty * 4];
            float4 b4 = *(const float4*)&Bs[cur][kk][tx * 4];
            float am[4] = {a4.x, a4.y, a4.z, a4.w};
            float bn[4] = {b4.x, b4.y, b4.z, b4.w};
#pragma unroll
            for (int i = 0; i < 4; i++)
#pragma unroll
                for (int jj = 0; jj < 4; jj++)
                    acc[i][jj] += am[i] * bn[jj];
        }
        if (more) {
            int nxt = cur ^ 1;
            if (BATCH) {
                *(float4*)&As[nxt][kA][j4] = ra;
            } else {
                As[nxt][ak4 + 0][arow] = ra.x; As[nxt][ak4 + 1][arow] = ra.y;
                As[nxt][ak4 + 2][arow] = ra.z; As[nxt][ak4 + 3][arow] = ra.w;
            }
            *(float4*)&Bs[nxt][kB][c4] = rb;
        }
        __syncthreads();
    }

    float4 eb4 = {0, 0, 0, 0};
    if (EMODE == 1) eb4 = *(const float4*)&eb[colBase + tx * 4];
#pragma unroll
    for (int i = 0; i < 4; i++) {
        int r = rowBase + ty * 4 + i;
        float4 v = {acc[i][0], acc[i][1], acc[i][2], acc[i][3]};
        if (EMODE == 1) {
            float sa = g_sA[r];
            v.x = fmaxf(v.x + sa * eb4.x, 0.f);
            v.y = fmaxf(v.y + sa * eb4.y, 0.f);
            v.z = fmaxf(v.z + sa * eb4.z, 0.f);
            v.w = fmaxf(v.w + sa * eb4.w, 0.f);
        } else if (EMODE == 2) {
            v.x = fmaxf(v.x, 0.f); v.y = fmaxf(v.y, 0.f);
            v.z = fmaxf(v.z, 0.f); v.w = fmaxf(v.w, 0.f);
        }
        *(float4*)&P[(size_t)r * ldp + colBase + tx * 4] = v;
    }
}

// ---------------------------------------------------------------------------
// final: out = (pO0+..+pO4 + Wu_b[n]) * w[r]
// ---------------------------------------------------------------------------
__global__ __launch_bounds__(256) void k_final(const float* __restrict__ Wub,
                                               const float* __restrict__ w,
                                               float* __restrict__ out) {
    int r = blockIdx.x, n = threadIdx.x;
    size_t idx = (size_t)r * NH + n;
    float s = g_pO[0][idx] + g_pO[1][idx] + g_pO[2][idx] + g_pO[3][idx] + g_pO[4][idx];
    out[idx] = (s + Wub[n]) * w[r];
}

// ---------------------------------------------------------------------------
extern "C" void kernel_launch(void* const* d_in, const int* in_sizes, int n_in,
                              void* d_out, int out_size) {
    const float* X    = (const float*)d_in[0];
    const float* E    = (const float*)d_in[1];
    const float* A    = (const float*)d_in[2];
    const float* w    = (const float*)d_in[3];
    const float* Wv_w = (const float*)d_in[4];
    const float* Wv_b = (const float*)d_in[5];
    const float* We_w = (const float*)d_in[6];
    const float* We_b = (const float*)d_in[7];
    const float* Wu_w = (const float*)d_in[8];
    const float* Wu_b = (const float*)d_in[9];
    float* out = (float*)d_out;

    float *p_aggE, *p_hE, *p_hN, *p_pNM, *p_pO;
    cudaGetSymbolAddress((void**)&p_aggE, g_aggE);
    cudaGetSymbolAddress((void**)&p_hE,   g_hE);
    cudaGetSymbolAddress((void**)&p_hN,   g_hN);
    cudaGetSymbolAddress((void**)&p_pNM,  g_pNM);
    cudaGetSymbolAddress((void**)&p_pO,   g_pO);
    const size_t SL = (size_t)RR * NH;
    float* pNM0 = p_pNM;
    float* pNM1 = p_pNM + SL;

    cudaStream_t sB, sC;
    cudaStreamCreateWithFlags(&sB, cudaStreamNonBlocking);
    cudaStreamCreateWithFlags(&sC, cudaStreamNonBlocking);
    cudaEvent_t e0, eB, eC;
    cudaEventCreateWithFlags(&e0, cudaEventDisableTiming);
    cudaEventCreateWithFlags(&eB, cudaEventDisableTiming);
    cudaEventCreateWithFlags(&eC, cudaEventDisableTiming);

    dim3 gZ2(RR / 64, NH / 64, 2);   // (32,4,2) = 256 CTAs
    dim3 gZ1(RR / 64, NH / 64, 1);   // (32,4)   = 128
    dim3 gHE(RR / 64, EH / 64, 1);   // (32,2)   = 64

    cudaEventRecord(e0, 0);
    cudaStreamWaitEvent(sB, e0, 0);
    cudaStreamWaitEvent(sC, e0, 0);

    // ---- sB: edge chain (persistent agge co-runs with GEMMs below) ----
    k_agge<<<512, 256, 0, sB>>>(A, E);
    // hE = relu(aggE @ We + sA*We_b), K=128
    gmm<0,0,1,false><<<gHE, 256, 0, sB>>>(p_aggE, EH, We_w, nullptr, EH,
                                          nullptr, We_b, p_hE, EH, 0, 0, 0, 8);
    // pO[4] = hE @ Wu[256:384], K=128
    gmm<0,0,0,false><<<gZ1, 256, 0, sB>>>(p_hE, EH, Wu_w, nullptr, NH,
                                          nullptr, nullptr, p_pO + 4 * SL, NH, 0, 0, 256, 8);
    cudaEventRecord(eB, sB);

    // ---- sC: X branch: relu(X) @ Wu[384:640] -> pO[2],pO[3], K=256 z=2 ----
    gmm<1,0,0,false><<<gZ2, 256, 0, sC>>>(X, NH, Wu_w, nullptr, NH,
                                          nullptr, nullptr, p_pO + 2 * SL, NH, SL, 0, 384, 8);
    cudaEventRecord(eC, sC);

    // ---- s0: node chain ----
    // pNM[0..1] = X @ Wv, K=256 z=2
    gmm<0,0,0,false><<<gZ2, 256>>>(X, NH, Wv_w, nullptr, NH,
                                   nullptr, nullptr, p_pNM, NH, SL, 0, 0, 8);
    // hN = relu( A^T @ (pNM0+pNM1+Wv_b) ), per-batch, K(i)=128 (bias rides through)
    gmm<0,1,2,true><<<gZ1, 256>>>(A, MM, pNM0, pNM1, NH,
                                  Wv_b, nullptr, p_hN, NH, 0, 0, 0, 8);
    // pO[0],pO[1] = hN @ Wu[0:256], K=256 z=2
    gmm<0,0,0,false><<<gZ2, 256>>>(p_hN, NH, Wu_w, nullptr, NH,
                                   nullptr, nullptr, p_pO, NH, SL, 0, 0, 8);

    // ---- join + epilogue ----
    cudaStreamWaitEvent(0, eB, 0);
    cudaStreamWaitEvent(0, eC, 0);
    k_final<<<RR, 256>>>(Wu_b, w, out);

    cudaEventDestroy(e0); cudaEventDestroy(eB); cudaEventDestroy(eC);
    cudaStreamDestroy(sB); cudaStreamDestroy(sC);
}